// round 17
// baseline (speedup 1.0000x reference)
#include <cuda_runtime.h>
#include <math.h>

#define R_REG 2000
#define NHEAD 4
#define DIM   128
#define DH    32
#define NMAX  500000
#define WPITCH 132   // smem pitch (floats): conflict-free float4 row reads
#define K0_BLOCKS 296
#define K0_CHUNK 4096
#define ACC_BLOCKS 740   // persistent k_accum blocks

// ---------------- scratch (device globals; no allocation allowed) ----------------
__device__ float d_q[DIM];                      // PMA seed query (flattened)
__device__ float d_A[NHEAD * DIM];              // folded score matrix (incl 1/sqrt(D))
__device__ float d_c[NHEAD];                    // folded score bias
__device__ int   d_hist[R_REG];                 // zeroed by inline scan after reading (replay-safe)
__device__ int   d_starts[R_REG + 1];
__device__ int   d_cursor[R_REG];
__device__ int   d_order[NMAX + 16];            // +16 pad so prefetch needs no bounds checks
__device__ int   d_tick;                        // grid-barrier ticket (reset by scan block)
__device__ int   d_go;                          // scan-done flag (reset by last finisher)
__device__ int   d_done;                        // phase-2 completion counter
__device__ int   d_rctr;                        // dynamic region counter for k_accum
__device__ __align__(16) float d_u[R_REG * NHEAD * DIM];  // normalized weighted sums of x
__device__ float d_flag[R_REG];                 // 1 if region nonempty
__device__ float d_hbuf[R_REG * DIM];           // GCN h = O @ Wg^T
__device__ float d_deg[R_REG];

// ---------------- K0: persistent front kernel ----------------
// phase 1: init + setup + privatized histogram  ->  ticket (grid barrier, last block scans)
// phase 2 (after spin on d_go): counting-sort scatter + GCN degree count.  Flags reset for replay.
__global__ void __launch_bounds__(256) k_front(
        const float* __restrict__ bg, float* __restrict__ out,
        const float* __restrict__ S, const float* __restrict__ Wq,
        const float* __restrict__ bq, const float* __restrict__ Wk,
        const float* __restrict__ bk, const int* __restrict__ zone,
        const int* __restrict__ adj, int N, int E) {
    __shared__ int hs[R_REG];
    __shared__ int wsum[8];
    __shared__ float S_s[DIM];
    __shared__ float q_s[DIM];
    __shared__ int isLast;
    int t = threadIdx.x;
    int b = blockIdx.x;
    int G = gridDim.x;

    // ---- phase 1a: grid-stride init ----
    for (int i = b * 256 + t; i < R_REG * DIM; i += G * 256) out[i] = bg[i & (DIM - 1)];
    for (int i = b * 256 + t; i < R_REG; i += G * 256) d_deg[i] = 1.0f;
    if (b == 0) {
        if (t < 16) d_order[N + t] = 0;  // prefetch pad (valid index 0)
        if (t == 0) d_rctr = 0;          // reset dynamic counter (replay-safe)
    }

    // ---- phase 1b: seed-query setup on the last block (skips hist: b >= nCh) ----
    if (b == G - 1) {
        if (t < DIM) S_s[t] = S[t];
        __syncthreads();
        if (t < DIM) {
            float acc = bq[t];
            const float4* wrow = (const float4*)(Wq + t * DIM);
            const float4* s4 = (const float4*)S_s;
            #pragma unroll
            for (int i = 0; i < DIM / 4; i++) {
                float4 w = wrow[i]; float4 s = s4[i];
                acc = fmaf(w.x, s.x, acc); acc = fmaf(w.y, s.y, acc);
                acc = fmaf(w.z, s.z, acc); acc = fmaf(w.w, s.w, acc);
            }
            q_s[t] = acc;
            d_q[t] = acc;
        }
        __syncthreads();
        if (t < DIM) {
            const float invsq = 0.08838834764831845f;  // 1/sqrt(128)
            for (int h = 0; h < NHEAD; h++) {
                float a = 0.f;
                #pragma unroll 8
                for (int dh = 0; dh < DH; dh++)
                    a = fmaf(q_s[h * DH + dh], Wk[(h * DH + dh) * DIM + t], a);
                d_A[h * DIM + t] = a * invsq;
            }
            if (t < NHEAD) {
                float cc = 0.f;
                for (int dh = 0; dh < DH; dh++) cc = fmaf(q_s[t * DH + dh], bk[t * DH + dh], cc);
                d_c[t] = cc * invsq;
            }
        }
    }

    // ---- phase 1c: privatized histogram, grid-stride over chunks ----
    int nCh = (N + K0_CHUNK - 1) / K0_CHUNK;
    for (int c = b; c < nCh; c += G) {
        for (int i = t; i < R_REG; i += 256) hs[i] = 0;
        __syncthreads();
        int base = c * K0_CHUNK;
        int lim = min(K0_CHUNK, N - base);
        for (int i = t; i < lim; i += 256) atomicAdd(&hs[zone[base + i]], 1);
        __syncthreads();
        for (int i = t; i < R_REG; i += 256) {
            int v = hs[i];
            if (v) atomicAdd(&d_hist[i], v);
        }
        __syncthreads();
    }

    // ---- ticket: doubles as grid barrier; last block to arrive runs the scan ----
    if (t == 0) {
        __threadfence();
        isLast = (atomicAdd(&d_tick, 1) == G - 1) ? 1 : 0;
    }
    __syncthreads();
    if (isLast) {
        if (t == 0) d_tick = 0;   // reset for next replay
        // exclusive scan of d_hist (reads + resets), writes starts + cursor
        int sbase = t * 8;
        int vals[8]; int s = 0;
        #pragma unroll
        for (int i = 0; i < 8; i++) {
            int idx = sbase + i;
            int v = 0;
            if (idx < R_REG) { v = d_hist[idx]; d_hist[idx] = 0; }
            vals[i] = s; s += v;
        }
        int lane = t & 31, w = t >> 5;
        int inc = s;
        #pragma unroll
        for (int off = 1; off < 32; off <<= 1) {
            int o = __shfl_up_sync(0xffffffffu, inc, off);
            if (lane >= off) inc += o;
        }
        if (lane == 31) wsum[w] = inc;
        __syncthreads();
        if (t == 0) {
            int acc = 0;
            for (int i = 0; i < 8; i++) { int v = wsum[i]; wsum[i] = acc; acc += v; }
            d_starts[R_REG] = acc;
        }
        __syncthreads();
        int texcl = inc - s + wsum[w];
        #pragma unroll
        for (int i = 0; i < 8; i++) {
            int idx = sbase + i;
            if (idx < R_REG) {
                int st = texcl + vals[i];
                d_starts[idx] = st;
                d_cursor[idx] = st;
            }
        }
        __syncthreads();
        if (t == 0) { __threadfence(); atomicExch(&d_go, 1); }
    } else {
        if (t == 0) {
            while (atomicAdd(&d_go, 0) == 0) { __nanosleep(128); }
        }
        __syncthreads();
    }
    __threadfence();

    // ---- phase 2: counting-sort scatter (4 pts/thread) + degree count ----
    int nQuad = (N + 3) / 4;
    for (int q = b * 256 + t; q < nQuad; q += G * 256) {
        int base = q * 4;
        if (base + 3 < N) {
            int4 z = *(const int4*)(zone + base);
            int p0 = atomicAdd(&d_cursor[z.x], 1);
            int p1 = atomicAdd(&d_cursor[z.y], 1);
            int p2 = atomicAdd(&d_cursor[z.z], 1);
            int p3 = atomicAdd(&d_cursor[z.w], 1);
            d_order[p0] = base;
            d_order[p1] = base + 1;
            d_order[p2] = base + 2;
            d_order[p3] = base + 3;
        } else {
            for (int n = base; n < N; n++) {
                int pos = atomicAdd(&d_cursor[zone[n]], 1);
                d_order[pos] = n;
            }
        }
    }
    for (int e = b * 256 + t; e < E; e += G * 256)
        atomicAdd(&d_deg[adj[E + e]], 1.0f);

    // ---- reset flags for next graph replay (last finisher) ----
    __syncthreads();
    if (t == 0) {
        __threadfence();
        if (atomicAdd(&d_done, 1) == G - 1) {
            d_done = 0;
            atomicExch(&d_go, 0);
        }
    }
}

// 4-head warp reduction in 9 shfls; ALL lanes of 8-lane group g end with head-g's full sum
__device__ __forceinline__ float headred(float s0, float s1, float s2, float s3, int lane) {
    float o0 = __shfl_xor_sync(0xffffffffu, s0, 16);
    float o1 = __shfl_xor_sync(0xffffffffu, s1, 16);
    float o2 = __shfl_xor_sync(0xffffffffu, s2, 16);
    float o3 = __shfl_xor_sync(0xffffffffu, s3, 16);
    float t0, t1;
    if (lane < 16) { t0 = s0 + o0; t1 = s1 + o1; } else { t0 = s2 + o2; t1 = s3 + o3; }
    float p0 = __shfl_xor_sync(0xffffffffu, t0, 8);
    float p1 = __shfl_xor_sync(0xffffffffu, t1, 8);
    float v = ((lane & 8) == 0) ? (t0 + p0) : (t1 + p1);
    v += __shfl_xor_sync(0xffffffffu, v, 4);
    v += __shfl_xor_sync(0xffffffffu, v, 2);
    v += __shfl_xor_sync(0xffffffffu, v, 1);
    return v;
}

// ---------------- K1: persistent single-pass score + weighted accumulation ----------------
// 740 resident blocks pull regions off a global counter.  minBlocks=6 caps regs for +occupancy.
__global__ void __launch_bounds__(128, 6) k_accum(const float* __restrict__ x) {
    int t = threadIdx.x;
    int w = t >> 5, lane = t & 31;
    const float4* x4 = (const float4*)x;
    const float4* A4 = (const float4*)d_A;
    float4 A0 = A4[0 * 32 + lane], A1 = A4[1 * 32 + lane];
    float4 A2 = A4[2 * 32 + lane], A3 = A4[3 * 32 + lane];
    float cb = d_c[lane >> 3];   // head bias (head = lane>>3); v holds that head's sum
    __shared__ float4 part[4][4][32];
    __shared__ float pdn[4][4];
    __shared__ int sreg;
    #define DOT4(a, v) ((a).x*(v).x + (a).y*(v).y + (a).z*(v).z + (a).w*(v).w)
    while (true) {
        if (t == 0) sreg = atomicAdd(&d_rctr, 1);
        __syncthreads();
        int r = sreg;
        if (r >= R_REG) break;
        int start = d_starts[r], end = d_starts[r + 1];
        float4 a0 = make_float4(0.f,0.f,0.f,0.f), a1 = a0, a2 = a0, a3 = a0;
        float dn0 = 0.f, dn1 = 0.f, dn2 = 0.f, dn3 = 0.f;
        int p = start + 4 * w;
        // unconditional preload (d_order padded by 16 zeroed entries)
        int n0 = __ldg(&d_order[p]);
        int n1 = __ldg(&d_order[p + 1]);
        int n2 = __ldg(&d_order[p + 2]);
        int n3 = __ldg(&d_order[p + 3]);
        #pragma unroll 1
        while (p + 4 <= end) {
            // 4 independent x-row gathers (2KB in flight per warp)
            float4 xv0 = __ldg(&x4[(size_t)n0 * 32 + lane]);
            float4 xv1 = __ldg(&x4[(size_t)n1 * 32 + lane]);
            float4 xv2 = __ldg(&x4[(size_t)n2 * 32 + lane]);
            float4 xv3 = __ldg(&x4[(size_t)n3 * 32 + lane]);
            // unguarded prefetch of next quad (pad-safe)
            int pn = p + 16;
            n0 = __ldg(&d_order[pn]);
            n1 = __ldg(&d_order[pn + 1]);
            n2 = __ldg(&d_order[pn + 2]);
            n3 = __ldg(&d_order[pn + 3]);
            // 4 interleaved score reductions (shfl latencies hide each other)
            float v0 = headred(DOT4(A0,xv0), DOT4(A1,xv0), DOT4(A2,xv0), DOT4(A3,xv0), lane);
            float v1 = headred(DOT4(A0,xv1), DOT4(A1,xv1), DOT4(A2,xv1), DOT4(A3,xv1), lane);
            float v2 = headred(DOT4(A0,xv2), DOT4(A1,xv2), DOT4(A2,xv2), DOT4(A3,xv2), lane);
            float v3 = headred(DOT4(A0,xv3), DOT4(A1,xv3), DOT4(A2,xv3), DOT4(A3,xv3), lane);
            float ev0 = __expf(v0 + cb);
            float ev1 = __expf(v1 + cb);
            float ev2 = __expf(v2 + cb);
            float ev3 = __expf(v3 + cb);
            float e00 = __shfl_sync(0xffffffffu, ev0, 0);
            float e01 = __shfl_sync(0xffffffffu, ev0, 8);
            float e02 = __shfl_sync(0xffffffffu, ev0, 16);
            float e03 = __shfl_sync(0xffffffffu, ev0, 24);
            float e10 = __shfl_sync(0xffffffffu, ev1, 0);
            float e11 = __shfl_sync(0xffffffffu, ev1, 8);
            float e12 = __shfl_sync(0xffffffffu, ev1, 16);
            float e13 = __shfl_sync(0xffffffffu, ev1, 24);
            float e20 = __shfl_sync(0xffffffffu, ev2, 0);
            float e21 = __shfl_sync(0xffffffffu, ev2, 8);
            float e22 = __shfl_sync(0xffffffffu, ev2, 16);
            float e23 = __shfl_sync(0xffffffffu, ev2, 24);
            float e30 = __shfl_sync(0xffffffffu, ev3, 0);
            float e31 = __shfl_sync(0xffffffffu, ev3, 8);
            float e32 = __shfl_sync(0xffffffffu, ev3, 16);
            float e33 = __shfl_sync(0xffffffffu, ev3, 24);
            a0.x = fmaf(e00, xv0.x, a0.x); a0.y = fmaf(e00, xv0.y, a0.y);
            a0.z = fmaf(e00, xv0.z, a0.z); a0.w = fmaf(e00, xv0.w, a0.w);
            a1.x = fmaf(e01, xv0.x, a1.x); a1.y = fmaf(e01, xv0.y, a1.y);
            a1.z = fmaf(e01, xv0.z, a1.z); a1.w = fmaf(e01, xv0.w, a1.w);
            a2.x = fmaf(e02, xv0.x, a2.x); a2.y = fmaf(e02, xv0.y, a2.y);
            a2.z = fmaf(e02, xv0.z, a2.z); a2.w = fmaf(e02, xv0.w, a2.w);
            a3.x = fmaf(e03, xv0.x, a3.x); a3.y = fmaf(e03, xv0.y, a3.y);
            a3.z = fmaf(e03, xv0.z, a3.z); a3.w = fmaf(e03, xv0.w, a3.w);
            dn0 += e00; dn1 += e01; dn2 += e02; dn3 += e03;
            a0.x = fmaf(e10, xv1.x, a0.x); a0.y = fmaf(e10, xv1.y, a0.y);
            a0.z = fmaf(e10, xv1.z, a0.z); a0.w = fmaf(e10, xv1.w, a0.w);
            a1.x = fmaf(e11, xv1.x, a1.x); a1.y = fmaf(e11, xv1.y, a1.y);
            a1.z = fmaf(e11, xv1.z, a1.z); a1.w = fmaf(e11, xv1.w, a1.w);
            a2.x = fmaf(e12, xv1.x, a2.x); a2.y = fmaf(e12, xv1.y, a2.y);
            a2.z = fmaf(e12, xv1.z, a2.z); a2.w = fmaf(e12, xv1.w, a2.w);
            a3.x = fmaf(e13, xv1.x, a3.x); a3.y = fmaf(e13, xv1.y, a3.y);
            a3.z = fmaf(e13, xv1.z, a3.z); a3.w = fmaf(e13, xv1.w, a3.w);
            dn0 += e10; dn1 += e11; dn2 += e12; dn3 += e13;
            a0.x = fmaf(e20, xv2.x, a0.x); a0.y = fmaf(e20, xv2.y, a0.y);
            a0.z = fmaf(e20, xv2.z, a0.z); a0.w = fmaf(e20, xv2.w, a0.w);
            a1.x = fmaf(e21, xv2.x, a1.x); a1.y = fmaf(e21, xv2.y, a1.y);
            a1.z = fmaf(e21, xv2.z, a1.z); a1.w = fmaf(e21, xv2.w, a1.w);
            a2.x = fmaf(e22, xv2.x, a2.x); a2.y = fmaf(e22, xv2.y, a2.y);
            a2.z = fmaf(e22, xv2.z, a2.z); a2.w = fmaf(e22, xv2.w, a2.w);
            a3.x = fmaf(e23, xv2.x, a3.x); a3.y = fmaf(e23, xv2.y, a3.y);
            a3.z = fmaf(e23, xv2.z, a3.z); a3.w = fmaf(e23, xv2.w, a3.w);
            dn0 += e20; dn1 += e21; dn2 += e22; dn3 += e23;
            a0.x = fmaf(e30, xv3.x, a0.x); a0.y = fmaf(e30, xv3.y, a0.y);
            a0.z = fmaf(e30, xv3.z, a0.z); a0.w = fmaf(e30, xv3.w, a0.w);
            a1.x = fmaf(e31, xv3.x, a1.x); a1.y = fmaf(e31, xv3.y, a1.y);
            a1.z = fmaf(e31, xv3.z, a1.z); a1.w = fmaf(e31, xv3.w, a1.w);
            a2.x = fmaf(e32, xv3.x, a2.x); a2.y = fmaf(e32, xv3.y, a2.y);
            a2.z = fmaf(e32, xv3.z, a2.z); a2.w = fmaf(e32, xv3.w, a2.w);
            a3.x = fmaf(e33, xv3.x, a3.x); a3.y = fmaf(e33, xv3.y, a3.y);
            a3.z = fmaf(e33, xv3.z, a3.z); a3.w = fmaf(e33, xv3.w, a3.w);
            dn0 += e30; dn1 += e31; dn2 += e32; dn3 += e33;
            p = pn;
        }
        // tail: up to 3 leftover points for this warp
        for (int q = p; q < end && q < p + 4; q++) {
            int n = __ldg(&d_order[q]);
            float4 xv = __ldg(&x4[(size_t)n * 32 + lane]);
            float v = headred(DOT4(A0,xv), DOT4(A1,xv), DOT4(A2,xv), DOT4(A3,xv), lane);
            float ev = __expf(v + cb);
            float e0 = __shfl_sync(0xffffffffu, ev, 0);
            float e1 = __shfl_sync(0xffffffffu, ev, 8);
            float e2 = __shfl_sync(0xffffffffu, ev, 16);
            float e3 = __shfl_sync(0xffffffffu, ev, 24);
            a0.x = fmaf(e0, xv.x, a0.x); a0.y = fmaf(e0, xv.y, a0.y);
            a0.z = fmaf(e0, xv.z, a0.z); a0.w = fmaf(e0, xv.w, a0.w);
            a1.x = fmaf(e1, xv.x, a1.x); a1.y = fmaf(e1, xv.y, a1.y);
            a1.z = fmaf(e1, xv.z, a1.z); a1.w = fmaf(e1, xv.w, a1.w);
            a2.x = fmaf(e2, xv.x, a2.x); a2.y = fmaf(e2, xv.y, a2.y);
            a2.z = fmaf(e2, xv.z, a2.z); a2.w = fmaf(e2, xv.w, a2.w);
            a3.x = fmaf(e3, xv.x, a3.x); a3.y = fmaf(e3, xv.y, a3.y);
            a3.z = fmaf(e3, xv.z, a3.z); a3.w = fmaf(e3, xv.w, a3.w);
            dn0 += e0; dn1 += e1; dn2 += e2; dn3 += e3;
        }
        // cross-warp combine in smem: part[warp][head][lane]
        part[w][0][lane] = a0; part[w][1][lane] = a1;
        part[w][2][lane] = a2; part[w][3][lane] = a3;
        if (lane == 0) { pdn[w][0] = dn0; pdn[w][1] = dn1; pdn[w][2] = dn2; pdn[w][3] = dn3; }
        __syncthreads();
        // thread t = (h=w, lane) finalizes head w
        int h = w;
        float4 s0 = part[0][h][lane], s1 = part[1][h][lane];
        float4 s2 = part[2][h][lane], s3 = part[3][h][lane];
        float4 u;
        u.x = s0.x + s1.x + s2.x + s3.x;
        u.y = s0.y + s1.y + s2.y + s3.y;
        u.z = s0.z + s1.z + s2.z + s3.z;
        u.w = s0.w + s1.w + s2.w + s3.w;
        float dn = pdn[0][h] + pdn[1][h] + pdn[2][h] + pdn[3][h];
        float inv = dn > 0.f ? 1.0f / dn : 0.f;
        u.x *= inv; u.y *= inv; u.z *= inv; u.w *= inv;
        ((float4*)d_u)[(size_t)r * 128 + h * 32 + lane] = u;
        if (t == 0) d_flag[r] = (end > start) ? 1.0f : 0.0f;
        __syncthreads();   // part[] safe to reuse; sreg safe to rewrite
    }
    #undef DOT4
}

// ---------------- K2: batched epilogue (R16 structure, proven correct) ----------------
__global__ void __launch_bounds__(512) k_epilogue(
        const float* __restrict__ Wv, const float* __restrict__ bv,
        const float* __restrict__ Wo, const float* __restrict__ bo,
        const float* __restrict__ Wg) {
    extern __shared__ float sm[];
    float* Wv_s = sm;
    float* Wo_s = Wv_s + DIM * WPITCH;
    float* Wg_s = Wo_s + DIM * WPITCH;
    float* O_s  = Wg_s + DIM * WPITCH;   // 16 regions x 128
    float* O2_s = O_s + 16 * DIM;        // 16 regions x 128
    int t = threadIdx.x;
    int grp = t >> 8;          // 0..1
    int tl = t & 255;          // thread in group
    int row = tl & 127;        // weight row / output element
    int half = tl >> 7;        // which 4 of the group's 8 regions
    int h = row >> 5;
    for (int idx = t; idx < DIM * DIM / 4; idx += 512) {
        int r4 = idx >> 5, col4 = idx & 31;
        float4 v0 = ((const float4*)Wv)[idx];
        float4 v1 = ((const float4*)Wo)[idx];
        float4 v2 = ((const float4*)Wg)[idx];
        *(float4*)(Wv_s + r4 * WPITCH + col4 * 4) = v0;
        *(float4*)(Wo_s + r4 * WPITCH + col4 * 4) = v1;
        *(float4*)(Wg_s + r4 * WPITCH + col4 * 4) = v2;
    }
    float qv = d_q[row], bvv = bv[row], bov = bo[row];
    int rbase = blockIdx.x * 16 + grp * 8 + half * 4;
    int slot = grp * 8 + half * 4;
    __syncthreads();
    // ---- stage 1: O = q + Wv . u + flag*bv ----
    {
        const float4* wr = (const float4*)(Wv_s + row * WPITCH);
        const float4* u0 = (const float4*)(d_u + (size_t)(rbase + 0) * 512 + h * 128);
        const float4* u1 = (const float4*)(d_u + (size_t)(rbase + 1) * 512 + h * 128);
        const float4* u2 = (const float4*)(d_u + (size_t)(rbase + 2) * 512 + h * 128);
        const float4* u3 = (const float4*)(d_u + (size_t)(rbase + 3) * 512 + h * 128);
        float a0 = 0.f, a1 = 0.f, a2 = 0.f, a3 = 0.f;
        #pragma unroll
        for (int i = 0; i < DIM / 4; i++) {
            float4 w = wr[i];
            float4 v0 = __ldg(&u0[i]);
            float4 v1 = __ldg(&u1[i]);
            float4 v2 = __ldg(&u2[i]);
            float4 v3 = __ldg(&u3[i]);
            a0 = fmaf(w.x, v0.x, a0); a0 = fmaf(w.y, v0.y, a0);
            a0 = fmaf(w.z, v0.z, a0); a0 = fmaf(w.w, v0.w, a0);
            a1 = fmaf(w.x, v1.x, a1); a1 = fmaf(w.y, v1.y, a1);
            a1 = fmaf(w.z, v1.z, a1); a1 = fmaf(w.w, v1.w, a1);
            a2 = fmaf(w.x, v2.x, a2); a2 = fmaf(w.y, v2.y, a2);
            a2 = fmaf(w.z, v2.z, a2); a2 = fmaf(w.w, v2.w, a2);
            a3 = fmaf(w.x, v3.x, a3); a3 = fmaf(w.y, v3.y, a3);
            a3 = fmaf(w.z, v3.z, a3); a3 = fmaf(w.w, v3.w, a3);
        }
        O_s[(slot + 0) * DIM + row] = qv + a0 + d_flag[rbase + 0] * bvv;
        O_s[(slot + 1) * DIM + row] = qv + a1 + d_flag[rbase + 1] * bvv;
        O_s[(slot + 2) * DIM + row] = qv + a2 + d_flag[rbase + 2] * bvv;
        O_s[(slot + 3) * DIM + row] = qv + a3 + d_flag[rbase + 3] * bvv;
    }
    asm volatile("bar.sync %0, %1;" :: "r"(grp + 1), "r"(256) : "memory");
    // ---- stage 2: O2 = O + relu(Wo . O + bo) ----
    {
        const float4* wr = (const float4*)(Wo_s + row * WPITCH);
        const float4* o0 = (const float4*)(O_s + (slot + 0) * DIM);
        const float4* o1 = (const float4*)(O_s + (slot + 1) * DIM);
        const float4* o2 = (const float4*)(O_s + (slot + 2) * DIM);
        const float4* o3 = (const float4*)(O_s + (slot + 3) * DIM);
        float a0 = bov, a1 = bov, a2 = bov, a3 = bov;
        #pragma unroll
        for (int i = 0; i < DIM / 4; i++) {
            float4 w = wr[i];
            float4 v0 = o0[i];
            float4 v1 = o1[i];
            float4 v2 = o2[i];
            float4 v3 = o3[i];
            a0 = fmaf(w.x, v0.x, a0); a0 = fmaf(w.y, v0.y, a0);
            a0 = fmaf(w.z, v0.z, a0); a0 = fmaf(w.w, v0.w, a0);
            a1 = fmaf(w.x, v1.x, a1); a1 = fmaf(w.y, v1.y, a1);
            a1 = fmaf(w.z, v1.z, a1); a1 = fmaf(w.w, v1.w, a1);
            a2 = fmaf(w.x, v2.x, a2); a2 = fmaf(w.y, v2.y, a2);
            a2 = fmaf(w.z, v2.z, a2); a2 = fmaf(w.w, v2.w, a2);
            a3 = fmaf(w.x, v3.x, a3); a3 = fmaf(w.y, v3.y, a3);
            a3 = fmaf(w.z, v3.z, a3); a3 = fmaf(w.w, v3.w, a3);
        }
        O2_s[(slot + 0) * DIM + row] = O_s[(slot + 0) * DIM + row] + fmaxf(a0, 0.f);
        O2_s[(slot + 1) * DIM + row] = O_s[(slot + 1) * DIM + row] + fmaxf(a1, 0.f);
        O2_s[(slot + 2) * DIM + row] = O_s[(slot + 2) * DIM + row] + fmaxf(a2, 0.f);
        O2_s[(slot + 3) * DIM + row] = O_s[(slot + 3) * DIM + row] + fmaxf(a3, 0.f);
    }
    asm volatile("bar.sync %0, %1;" :: "r"(grp + 1), "r"(256) : "memory");
    // ---- stage 3: h = Wg . O2 -> global ----
    {
        const float4* wr = (const float4*)(Wg_s + row * WPITCH);
        const float4* o0 = (const float4*)(O2_s + (slot + 0) * DIM);
        const float4* o1 = (const float4*)(O2_s + (slot + 1) * DIM);
        const float4* o2 = (const float4*)(O2_s + (slot + 2) * DIM);
        const float4* o3 = (const float4*)(O2_s + (slot + 3) * DIM);
        float a0 = 0.f, a1 = 0.f, a2 = 0.f, a3 = 0.f;
        #pragma unroll
        for (int i = 0; i < DIM / 4; i++) {
            float4 w = wr[i];
            float4 v0 = o0[i];
            float4 v1 = o1[i];
            float4 v2 = o2[i];
            float4 v3 = o3[i];
            a0 = fmaf(w.x, v0.x, a0); a0 = fmaf(w.y, v0.y, a0);
            a0 = fmaf(w.z, v0.z, a0); a0 = fmaf(w.w, v0.w, a0);
            a1 = fmaf(w.x, v1.x, a1); a1 = fmaf(w.y, v1.y, a1);
            a1 = fmaf(w.z, v1.z, a1); a1 = fmaf(w.w, v1.w, a1);
            a2 = fmaf(w.x, v2.x, a2); a2 = fmaf(w.y, v2.y, a2);
            a2 = fmaf(w.z, v2.z, a2); a2 = fmaf(w.w, v2.w, a2);
            a3 = fmaf(w.x, v3.x, a3); a3 = fmaf(w.y, v3.y, a3);
            a3 = fmaf(w.z, v3.z, a3); a3 = fmaf(w.w, v3.w, a3);
        }
        d_hbuf[(size_t)(rbase + 0) * DIM + row] = a0;
        d_hbuf[(size_t)(rbase + 1) * DIM + row] = a1;
        d_hbuf[(size_t)(rbase + 2) * DIM + row] = a2;
        d_hbuf[(size_t)(rbase + 3) * DIM + row] = a3;
    }
}

// ---------------- K3: edge scatter out[dst] += norm * h[src] (warp per edge) ----------------
__global__ void k_edge(const int* __restrict__ adj, int E, float* __restrict__ out) {
    int widx = (blockIdx.x * blockDim.x + threadIdx.x) >> 5;
    int lane = threadIdx.x & 31;
    if (widx >= E) return;
    int s = adj[widx], d = adj[E + widx];
    float norm = rsqrtf(fmaxf(d_deg[s], 1e-12f)) * rsqrtf(fmaxf(d_deg[d], 1e-12f));
    const float* hr = d_hbuf + (size_t)s * DIM;
    float* orow = out + (size_t)d * DIM;
    #pragma unroll
    for (int j = lane; j < DIM; j += 32)
        atomicAdd(&orow[j], norm * hr[j]);
}

// ---------------- K4: self loop + PReLU ----------------
__global__ void k_final(const float* __restrict__ prelu, float* __restrict__ out) {
    int idx = blockIdx.x * blockDim.x + threadIdx.x;
    if (idx >= R_REG * DIM) return;
    int r = idx >> 7, j = idx & 127;
    float dis = rsqrtf(fmaxf(d_deg[r], 1e-12f));
    float val = out[idx] + dis * dis * d_hbuf[idx];
    out[idx] = val > 0.f ? val : prelu[j] * val;
}

// ---------------- launch ----------------
extern "C" void kernel_launch(void* const* d_in, const int* in_sizes, int n_in,
                              void* d_out, int out_size) {
    const float* x    = (const float*)d_in[0];
    const int*   zone = (const int*)d_in[1];
    const int*   adj  = (const int*)d_in[2];
    const float* S    = (const float*)d_in[3];
    const float* Wq   = (const float*)d_in[4];
    const float* bq   = (const float*)d_in[5];
    const float* Wk   = (const float*)d_in[6];
    const float* bk   = (const float*)d_in[7];
    const float* Wv   = (const float*)d_in[8];
    const float* bv   = (const float*)d_in[9];
    const float* Wo   = (const float*)d_in[10];
    const float* bo   = (const float*)d_in[11];
    const float* Wg   = (const float*)d_in[12];
    const float* bg   = (const float*)d_in[13];
    const float* prelu = (const float*)d_in[14];
    float* out = (float*)d_out;
    int N = in_sizes[0] / DIM;
    int E = in_sizes[2] / 2;

    // K0: persistent front — init + hist + inline scan (grid barrier) + scatter + deg
    k_front<<<K0_BLOCKS, 256>>>(bg, out, S, Wq, bq, Wk, bk, zone, adj, N, E);

    // K1: persistent fused score+accumulate — dynamic region stealing
    k_accum<<<ACC_BLOCKS, 128>>>(x);

    // K2: batched epilogue — 16 regions per 512-thread block
    int smem_epi = (3 * DIM * WPITCH + 32 * DIM) * (int)sizeof(float);
    cudaFuncSetAttribute(k_epilogue, cudaFuncAttributeMaxDynamicSharedMemorySize, smem_epi);
    k_epilogue<<<R_REG / 16, 512, smem_epi>>>(Wv, bv, Wo, bo, Wg);

    k_edge<<<(E * 32 + 255) / 256, 256>>>(adj, E, out);
    k_final<<<(R_REG * DIM + 255) / 256, 256>>>(prelu, out);
}